// round 16
// baseline (speedup 1.0000x reference)
#include <cuda_runtime.h>

#define BS      16
#define NANCH   33600
#define NV4     8400
#define NCH     56
#define KTOP    3000
#define NB      4096
#define MAXDET  300
#define CONF_T  0.25f
#define IOU_T   0.7f
#define IMGW    1280.0f
#define FULLM   0xFFFFFFFFu
#define BPIM    8
#define NSEL    512
#define NSRT    1024
#define NW      16      // NSEL / 32
#define LCAPE   336
#define BCAP    48
#define SKCAP   1152

// ---------------- global scratch (L2-resident) ----------------
__device__ unsigned long long g_bins  [(size_t)BS * NB * BCAP];  // slots < fresh count read only
__device__ unsigned long long g_ksort [BS * NSRT];    // fully rewritten each replay
__device__ int                g_ntot  [BS];
__device__ float4             g_b512  [BS * NSEL];
__device__ float              g_a512  [BS * NSEL];
__device__ unsigned           g_mat   [BS * NSEL * NW];
__device__ unsigned           g_done3 [BS];            // ticket, self-resetting
__device__ int                g_cnt   [BS];
__device__ float4             g_selbox  [BS * MAXDET];
__device__ float              g_selscore[BS * MAXDET];
__device__ int                g_selanch [BS * MAXDET];

__device__ __forceinline__ unsigned ordkey(float f) {
    unsigned b = __float_as_uint(f);
    return (b & 0x80000000u) ? ~b : (b | 0x80000000u);
}
__device__ __forceinline__ float inv_ordkey(unsigned u) {
    unsigned bits = (u & 0x80000000u) ? (u & 0x7FFFFFFFu) : ~u;
    return __uint_as_float(bits);
}
__device__ __forceinline__ int bucket_of(float s) {
    int b = (int)(s * 4096.0f);
    return min(4095, max(0, b));
}
// suppression test, bit-identical to reference rounding (rel_err=0 R1..R14)
__device__ __forceinline__ bool sup_test(float ax, float ay, float az, float aw, float aa,
                                         float bx, float by, float bz, float bw, float ab) {
    float xx1 = fmaxf(ax, bx);
    float yy1 = fmaxf(ay, by);
    float xx2 = fminf(az, bz);
    float yy2 = fminf(aw, bw);
    float ww  = fmaxf(xx2 - xx1, 0.0f);
    float hh  = fmaxf(yy2 - yy1, 0.0f);
    float inter = __fmul_rn(ww, hh);
    if (inter <= 0.0f) return false;
    float denom = __fadd_rn(__fsub_rn(__fadd_rn(aa, ab), inter), 1e-9f);
    return (inter / denom) > IOU_T;
}
__device__ __forceinline__ void decode_box(const float* pimg, unsigned long long key,
                                           float4& b, float& area) {
    int anchor = 65535 - (int)(key & 0xFFFFull);
    anchor = min(anchor, NANCH - 1);
    float cx = pimg[anchor];
    float cy = pimg[(size_t)NANCH + anchor];
    float w  = pimg[2 * (size_t)NANCH + anchor];
    float ht = pimg[3 * (size_t)NANCH + anchor];
    float hw = w * 0.5f, hh = ht * 0.5f;
    b.x = fminf(fmaxf(cx - hw, 0.0f), IMGW);
    b.y = fminf(fmaxf(cy - hh, 0.0f), IMGW);
    b.z = fminf(fmaxf(cx + hw, 0.0f), IMGW);
    b.w = fminf(fmaxf(cy + hh, 0.0f), IMGW);
    area = __fmul_rn(b.z - b.x, b.w - b.y);
}

// ================= K1: single-pass binned select + top-1024 rank (one block/image) =================
// smem: scnt[NB] 16KB | sstart[NB] 16KB | skeys[SKCAP] 9216B | ssort[NSRT] 8KB
#define F_SCNT  0
#define F_SST   16384
#define F_SKEY  32768
#define F_SSORT (F_SKEY + SKCAP * 8)
#define F_SMEM  (F_SSORT + NSRT * 8)
__global__ void __launch_bounds__(1024) k_front(const float* __restrict__ preds) {
    extern __shared__ char sm[];
    unsigned*           scnt   = (unsigned*)(sm + F_SCNT);
    unsigned*           sstart = (unsigned*)(sm + F_SST);
    unsigned long long* skeys  = (unsigned long long*)(sm + F_SKEY);
    unsigned long long* ssort  = (unsigned long long*)(sm + F_SSORT);
    __shared__ unsigned wsum[32];
    __shared__ int sbK, sbS;

    const int img  = blockIdx.x;
    const int tid  = threadIdx.x;
    const int lane = tid & 31;
    const int wid  = tid >> 5;
    const float*  pimg  = preds + (size_t)img * NCH * NANCH;
    const float4* conf4 = (const float4*)(pimg + 4 * (size_t)NANCH);

    ((uint4*)scnt)[tid] = make_uint4(0u, 0u, 0u, 0u);
    if (tid == 0) { sbK = 0; sbS = 0; }
    __syncthreads();

    // ---- single pass: count + write key into per-bucket bin ----
    for (int i = tid; i < NV4; i += 1024) {
        float4 v = conf4[i];
        float sv[4] = {v.x, v.y, v.z, v.w};
        int a = 4 * i;
        #pragma unroll
        for (int c = 0; c < 4; c++) {
            float s = sv[c];
            if (s > CONF_T) {
                int b = bucket_of(s);
                unsigned pos = atomicAdd(&scnt[b], 1u);
                if (pos < BCAP)
                    g_bins[((size_t)img * NB + b) * BCAP + pos] =
                        ((unsigned long long)ordkey(s) << 16) | (unsigned)(65535 - (a + c));
            }
        }
    }
    __syncthreads();

    // ---- suffix scan -> sstart + cutoffs (KTOP and NSRT) ----
    uint4 hv = ((const uint4*)scnt)[tid];
    unsigned tot = hv.x + hv.y + hv.z + hv.w;
    unsigned suf = tot;
    #pragma unroll
    for (int d = 1; d < 32; d <<= 1) {
        unsigned v = __shfl_down_sync(FULLM, suf, d);
        if (lane + d < 32) suf += v;
    }
    if (lane == 0) wsum[wid] = suf;
    __syncthreads();
    if (tid < 32) {
        unsigned v  = wsum[tid];
        unsigned sv = v;
        #pragma unroll
        for (int d = 1; d < 32; d <<= 1) {
            unsigned u = __shfl_down_sync(FULLM, sv, d);
            if (tid + d < 32) sv += u;
        }
        wsum[tid] = sv - v;
    }
    __syncthreads();
    unsigned run = wsum[wid] + (suf - tot);
    unsigned e3 = run;
    unsigned e2 = e3 + hv.w;
    unsigned e1 = e2 + hv.z;
    unsigned e0 = e1 + hv.y;
    ((uint4*)sstart)[tid] = make_uint4(e0, e1, e2, e3);
    if      (e3 + hv.w >= (unsigned)KTOP) atomicMax(&sbK, 4 * tid + 3);
    else if (e2 + hv.z >= (unsigned)KTOP) atomicMax(&sbK, 4 * tid + 2);
    else if (e1 + hv.y >= (unsigned)KTOP) atomicMax(&sbK, 4 * tid + 1);
    else if (e0 + hv.x >= (unsigned)KTOP) atomicMax(&sbK, 4 * tid + 0);
    if      (e3 + hv.w >= (unsigned)NSRT) atomicMax(&sbS, 4 * tid + 3);
    else if (e2 + hv.z >= (unsigned)NSRT) atomicMax(&sbS, 4 * tid + 2);
    else if (e1 + hv.y >= (unsigned)NSRT) atomicMax(&sbS, 4 * tid + 1);
    else if (e0 + hv.x >= (unsigned)NSRT) atomicMax(&sbS, 4 * tid + 0);
    // zero sorted buffer while waiting
    for (int r = tid; r < NSRT; r += 1024) ssort[r] = 0ull;
    __syncthreads();
    const int cutK = sbK;
    const int cutS = max(sbS, 1024);

    // ---- load keys of buckets >= cutS back into smem at their segment offsets ----
    {
        const int nslots = (NB - cutS) * BCAP;
        for (int idx = tid; idx < nslots; idx += 1024) {
            int b    = cutS + idx / BCAP;
            int slot = idx % BCAP;
            unsigned cnt = min(scnt[b], (unsigned)BCAP);
            if ((unsigned)slot < cnt) {
                unsigned pos = sstart[b] + slot;
                if (pos < SKCAP)
                    skeys[pos] = g_bins[((size_t)img * NB + b) * BCAP + slot];
            }
        }
    }
    __syncthreads();

    // ---- exact rank of top superset (~1070 keys) -> sorted top-1024 ----
    const int nsel_tot = min((int)(sstart[cutS] + min(scnt[cutS], (unsigned)BCAP)), SKCAP);
    for (int p = tid; p < nsel_tot; p += 1024) {
        unsigned long long key = skeys[p];
        float sc = inv_ordkey((unsigned)(key >> 16));
        int b   = bucket_of(sc);
        int st  = (int)sstart[b];
        int en  = min((int)(sstart[b] + min(scnt[b], (unsigned)BCAP)), SKCAP);
        int rank = st;
        for (int q = st; q < en; q++) rank += (skeys[q] > key) ? 1 : 0;
        if (rank < NSRT) ssort[rank] = key;
    }
    __syncthreads();

    // ---- publish sorted keys + decoded top-512 boxes ----
    for (int r = tid; r < NSRT; r += 1024)
        g_ksort[img * NSRT + r] = ssort[r];
    if (tid < NSEL) {
        float4 b; float ar;
        decode_box(pimg, ssort[tid], b, ar);
        g_b512[img * NSEL + tid] = b;
        g_a512[img * NSEL + tid] = ar;
    }
    if (tid == 0) {
        int ntot = (int)(sstart[cutK] + scnt[cutK]);
        g_ntot[img] = min(ntot, KTOP);
    }
}

// ================= K2: parallel 512x512 suppression matrix; last block resolves =================
// smem layout (bytes)
#define M_SBOX  0                        // 512*16 = 8192
#define M_SAREA 8192                     // 512*4  = 2048
#define M_SKEY  10240                    // 512*8  = 4096
#define M_SMAT  14336                    // 512*16*4 = 32768
#define M_LBOX  47104                    // 336*16 = 5376
#define M_LAREA 52480                    // 336*4  = 1344
#define M_LKEY  53824                    // 336*8  = 2688
#define M_TOTAL 56512

__global__ void __launch_bounds__(1024) k_matres(const float* __restrict__ preds) {
    extern __shared__ char sm[];
    float4*             sbox  = (float4*)(sm + M_SBOX);
    float*              sarea = (float*)(sm + M_SAREA);
    unsigned long long* skey  = (unsigned long long*)(sm + M_SKEY);
    unsigned*           smat  = (unsigned*)(sm + M_SMAT);
    float4*             lbox  = (float4*)(sm + M_LBOX);
    float*              slar  = (float*)(sm + M_LAREA);
    unsigned long long* lkey  = (unsigned long long*)(sm + M_LKEY);
    __shared__ unsigned sValid[NW], sSall[NW], sKept0[NW], sK0[NW], sKept[NW], sPref[NW];
    __shared__ int s_cur, slast;

    const int img  = blockIdx.x >> 3;
    const int part = blockIdx.x & 7;
    const int tid  = threadIdx.x;
    const int lane = tid & 31;
    const int w    = tid >> 5;
    const float* pimg = preds + (size_t)img * NCH * NANCH;
    const int ntot = g_ntot[img];

    // ---- load top-512 candidates (coalesced, decoded once in K1) ----
    if (tid < NSEL) {
        skey[tid]  = g_ksort[img * NSRT + tid];
        sbox[tid]  = g_b512[img * NSEL + tid];
        sarea[tid] = g_a512[img * NSEL + tid];
    }
    __syncthreads();

    // ---- slab of upper-triangular suppression matrix ----
    {
        const int cw   = w & 15;
        const int half = w >> 4;
        const int j    = cw * 32 + lane;
        float4 bj = sbox[j];
        float  aj = sarea[j];
        const int i0 = part * 64 + half * 32;
        #pragma unroll 4
        for (int r = 0; r < 32; r++) {
            const int i = i0 + r;
            if (cw >= (i >> 5)) {
                float4 bi = sbox[i];
                float  ai = sarea[i];
                bool bit = (j > i) && sup_test(bi.x, bi.y, bi.z, bi.w, ai,
                                               bj.x, bj.y, bj.z, bj.w, aj);
                unsigned bm = __ballot_sync(FULLM, bit);
                if (lane == 0) g_mat[((size_t)img * NSEL + i) * NW + cw] = bm;
            }
        }
    }
    __syncthreads();
    if (tid == 0) {
        __threadfence();
        slast = (atomicAdd(&g_done3[img], 1u) == BPIM - 1);
    }
    __syncthreads();
    if (!slast) return;

    // ---- last block: exact greedy resolve via bit algebra ----
    __threadfence();
    if (tid == 0) { g_done3[img] = 0u; s_cur = 0; }
    for (int idx = tid; idx < NSEL * NW; idx += 1024)
        smat[idx] = g_mat[(size_t)img * NSEL * NW + idx];
    __syncthreads();

    if (w < NW) {
        int c = w * 32 + lane;
        bool valid = (c < ntot) && (skey[c] != 0ull);
        unsigned vb = __ballot_sync(FULLM, valid);
        if (lane == 0) sValid[w] = vb;
    }
    __syncthreads();
    if (w < NW) {
        unsigned acc = 0;
        for (int k = 0; k <= w; k++) {
            int c = k * 32 + lane;
            if ((sValid[k] >> lane) & 1u) acc |= smat[c * NW + w];
        }
        acc = __reduce_or_sync(FULLM, acc);
        if (lane == 0) sSall[w] = acc;
    }
    __syncthreads();
    if (w < NW && lane == 0) sKept0[w] = sValid[w] & ~sSall[w];
    __syncthreads();
    if (w < NW) {
        unsigned acc = 0;
        for (int k = 0; k <= w; k++) {
            int c = k * 32 + lane;
            if ((sKept0[k] >> lane) & 1u) acc |= smat[c * NW + w];
        }
        acc = __reduce_or_sync(FULLM, acc);
        if (lane == 0) sK0[w] = acc;
    }
    __syncthreads();

    if (tid < 32) {
        unsigned Sck = 0;
        unsigned keptReg = 0;
        for (int m = 0; m < NW; m++) {
            unsigned cont = sValid[m] & sSall[m];
            unsigned kc = 0;
            while (cont) {
                int bit = __ffs(cont) - 1;
                cont &= cont - 1u;
                int c = m * 32 + bit;
                unsigned sckm = __shfl_sync(FULLM, Sck, m);
                bool suppressed = (((sK0[m] | sckm) >> bit) & 1u) != 0u;
                if (!suppressed) {
                    kc |= 1u << bit;
                    if (lane < NW && lane >= m) Sck |= smat[c * NW + lane];
                }
            }
            unsigned kw = (sValid[m] & ~sSall[m]) | kc;
            if (lane == m) keptReg = kw;
        }
        int cntw = __popc((lane < NW) ? keptReg : 0u);
        int inc = cntw;
        #pragma unroll
        for (int d = 1; d < 32; d <<= 1) {
            int v = __shfl_up_sync(FULLM, inc, d);
            if (lane >= d) inc += v;
        }
        if (lane < NW) { sKept[lane] = keptReg; sPref[lane] = inc - cntw; }
        if (lane == 31) s_cur = inc;
    }
    __syncthreads();

    if (tid < NSEL) {
        int wrd = tid >> 5;
        int l   = tid & 31;
        unsigned km = sKept[wrd];
        if ((km >> l) & 1u) {
            int rank = (int)sPref[wrd] + __popc(km & ((1u << l) - 1u));
            if (rank < LCAPE) {
                lbox[rank] = sbox[tid];
                slar[rank] = sarea[tid];
                lkey[rank] = skey[tid];
            }
        }
    }
    __syncthreads();

    // exact fallback within sorted top-1024 (never taken in practice)
    if (tid < 32) {
        int curf = s_cur;
        int lim  = min(ntot, NSRT);
        if (curf < MAXDET && lim > NSEL) {
            for (int c = NSEL; c < lim && curf < MAXDET; c++) {
                unsigned long long key = g_ksort[img * NSRT + c];
                if (key == 0ull) continue;
                float4 bc; float ac;
                decode_box(pimg, key, bc, ac);
                bool sup = false;
                for (int l = lane; l < curf; l += 32) {
                    float4 bl = lbox[l];
                    sup |= sup_test(bl.x, bl.y, bl.z, bl.w, slar[l],
                                    bc.x, bc.y, bc.z, bc.w, ac);
                }
                if (!__any_sync(FULLM, sup)) {
                    if (lane == 0 && curf < LCAPE) {
                        lbox[curf] = bc; slar[curf] = ac; lkey[curf] = key;
                    }
                    __syncwarp();
                    curf++;
                }
            }
        }
        if (lane == 0) s_cur = curf;
    }
    __syncthreads();

    const int cnt = min(s_cur, MAXDET);
    if (tid < cnt) {
        unsigned long long key = lkey[tid];
        g_selbox  [img * MAXDET + tid] = lbox[tid];
        g_selscore[img * MAXDET + tid] = inv_ordkey((unsigned)(key >> 16));
        g_selanch [img * MAXDET + tid] = 65535 - (int)(key & 0xFFFFull);
    }
    if (tid == 0) g_cnt[img] = cnt;
}

// ================= K3: wide output writer =================
#define TOTOUT (BS * MAXDET * 56)
__global__ void __launch_bounds__(1024) k_out(const float* __restrict__ preds,
                                              float* __restrict__ out) {
    int s = blockIdx.x * 1024 + threadIdx.x;
    if (s >= TOTOUT) return;
    const int img = s / (MAXDET * 56);
    const int rem = s % (MAXDET * 56);
    const int r   = rem / 56;
    const int f   = rem % 56;
    const int cnt = g_cnt[img];

    float v = 0.0f;
    if (r < cnt) {
        if (f < 4) {
            float4 b = g_selbox[img * MAXDET + r];
            v = (f == 0) ? b.x : (f == 1) ? b.y : (f == 2) ? b.z : b.w;
        } else if (f == 4) {
            v = g_selscore[img * MAXDET + r];
        } else {
            int c = f - 5;
            int a = g_selanch[img * MAXDET + r];
            v = preds[(size_t)img * NCH * NANCH + (size_t)(5 + c) * NANCH + a];
            if (c < 2) v = fminf(fmaxf(v, 0.0f), IMGW);
        }
    }
    const int OSC = BS * MAXDET * 4;
    const int OKP = OSC + BS * MAXDET;
    if (f < 4)       out[(img * MAXDET + r) * 4 + f] = v;
    else if (f == 4) out[OSC + img * MAXDET + r] = v;
    else             out[OKP + (img * MAXDET + r) * 51 + (f - 5)] = v;
}

// ---------------- launch ----------------
extern "C" void kernel_launch(void* const* d_in, const int* in_sizes, int n_in,
                              void* d_out, int out_size) {
    const float* preds = (const float*)d_in[0];
    float* out = (float*)d_out;
    cudaFuncSetAttribute(k_front,  cudaFuncAttributeMaxDynamicSharedMemorySize, F_SMEM);
    cudaFuncSetAttribute(k_matres, cudaFuncAttributeMaxDynamicSharedMemorySize, M_TOTAL);
    k_front <<<BS, 1024, F_SMEM>>>(preds);
    k_matres<<<BS * BPIM, 1024, M_TOTAL>>>(preds);
    k_out   <<<(TOTOUT + 1023) / 1024, 1024>>>(preds, out);
}

// round 17
// speedup vs baseline: 1.0942x; 1.0942x over previous
#include <cuda_runtime.h>

#define BS      16
#define NANCH   33600
#define NV4     8400
#define NCH     56
#define KTOP    3000
#define CAP     4096
#define NB      4096
#define MAXDET  300
#define CONF_T  0.25f
#define IOU_T   0.7f
#define IMGW    1280.0f
#define FULLM   0xFFFFFFFFu
#define BPIM    8
#define NSEL    512
#define NW      16      // NSEL / 32
#define LCAPE   336
#define ALLCAP  26624

// ---------------- global scratch (L2-resident) ----------------
__device__ unsigned long long g_all   [(size_t)BS * ALLCAP]; // only [0,nall) read, same-block
__device__ unsigned long long g_keys2 [BS * CAP];    // fully rewritten each replay
__device__ int                g_ntot  [BS];
__device__ float4             g_b512  [BS * NSEL];   // fully rewritten each replay
__device__ float              g_a512  [BS * NSEL];
__device__ unsigned           g_mat   [BS * NSEL * NW];
__device__ unsigned           g_done3 [BS];          // ticket, self-resetting
__device__ int                g_cnt   [BS];
__device__ float4             g_selbox  [BS * MAXDET];
__device__ float              g_selscore[BS * MAXDET];
__device__ int                g_selanch [BS * MAXDET];

__device__ __forceinline__ unsigned ordkey(float f) {
    unsigned b = __float_as_uint(f);
    return (b & 0x80000000u) ? ~b : (b | 0x80000000u);
}
__device__ __forceinline__ float inv_ordkey(unsigned u) {
    unsigned bits = (u & 0x80000000u) ? (u & 0x7FFFFFFFu) : ~u;
    return __uint_as_float(bits);
}
__device__ __forceinline__ int bucket_of(float s) {
    int b = (int)(s * 4096.0f);
    return min(4095, max(0, b));
}
// suppression test, bit-identical to reference rounding (rel_err=0 R1..R14)
__device__ __forceinline__ bool sup_test(float ax, float ay, float az, float aw, float aa,
                                         float bx, float by, float bz, float bw, float ab) {
    float xx1 = fmaxf(ax, bx);
    float yy1 = fmaxf(ay, by);
    float xx2 = fminf(az, bz);
    float yy2 = fminf(aw, bw);
    float ww  = fmaxf(xx2 - xx1, 0.0f);
    float hh  = fmaxf(yy2 - yy1, 0.0f);
    float inter = __fmul_rn(ww, hh);
    if (inter <= 0.0f) return false;
    float denom = __fadd_rn(__fsub_rn(__fadd_rn(aa, ab), inter), 1e-9f);
    return (inter / denom) > IOU_T;
}
__device__ __forceinline__ void decode_box(const float* pimg, unsigned long long key,
                                           float4& b, float& area) {
    int anchor = 65535 - (int)(key & 0xFFFFull);
    anchor = min(anchor, NANCH - 1);
    float cx = pimg[anchor];
    float cy = pimg[(size_t)NANCH + anchor];
    float w  = pimg[2 * (size_t)NANCH + anchor];
    float ht = pimg[3 * (size_t)NANCH + anchor];
    float hw = w * 0.5f, hh = ht * 0.5f;
    b.x = fminf(fmaxf(cx - hw, 0.0f), IMGW);
    b.y = fminf(fmaxf(cy - hh, 0.0f), IMGW);
    b.z = fminf(fmaxf(cx + hw, 0.0f), IMGW);
    b.w = fminf(fmaxf(cy + hh, 0.0f), IMGW);
    area = __fmul_rn(b.z - b.x, b.w - b.y);
}

// ================= K1: single conf pass (hist + list) + scan + scatter-from-list + rank =================
// smem: sh[NB] (hist->bstart) 16KB | scur[NB] 16KB | skeys[CAP] 32KB = 65536 B
#define F_SMEM (NB * 4 + NB * 4 + CAP * 8)
__global__ void __launch_bounds__(1024) k_front(const float* __restrict__ preds) {
    extern __shared__ char sm[];
    unsigned*           sh    = (unsigned*)sm;                  // hist -> bstart (in place)
    unsigned*           scur  = (unsigned*)(sm + NB * 4);       // write cursors
    unsigned long long* skeys = (unsigned long long*)(sm + 2 * NB * 4);
    __shared__ unsigned wsum[32];
    __shared__ int sb, s_nall;

    const int img  = blockIdx.x;
    const int tid  = threadIdx.x;
    const int lane = tid & 31;
    const int wid  = tid >> 5;
    const float*  pimg  = preds + (size_t)img * NCH * NANCH;
    const float4* conf4 = (const float4*)(pimg + 4 * (size_t)NANCH);
    unsigned long long* alist = g_all + (size_t)img * ALLCAP;

    // ---- phase 1: SINGLE conf pass — hist + compact candidate list ----
    ((uint4*)sh)[tid] = make_uint4(0u, 0u, 0u, 0u);
    if (tid == 0) { sb = 0; s_nall = 0; }
    __syncthreads();
    const int NITER = (NV4 + 1023) / 1024;   // 9, uniform across block (ballot-safe)
    for (int ii = 0; ii < NITER; ii++) {
        int i = ii * 1024 + tid;
        bool inb = (i < NV4);
        float4 v = make_float4(-1.f, -1.f, -1.f, -1.f);
        if (inb) v = conf4[i];
        float sv[4] = {v.x, v.y, v.z, v.w};
        int a = 4 * i;
        #pragma unroll
        for (int c = 0; c < 4; c++) {
            float s = sv[c];
            bool on = inb && (s > CONF_T);
            unsigned m = __ballot_sync(FULLM, on);
            if (m) {
                int leader = __ffs(m) - 1;
                unsigned base = 0;
                if (lane == leader) base = atomicAdd((unsigned*)&s_nall, __popc(m));
                base = __shfl_sync(FULLM, base, leader);
                if (on) {
                    atomicAdd(&sh[bucket_of(s)], 1u);
                    unsigned pos = base + __popc(m & ((1u << lane) - 1u));
                    if (pos < ALLCAP)
                        alist[pos] = ((unsigned long long)ordkey(s) << 16)
                                   | (unsigned)(65535 - (a + c));
                }
            }
        }
    }
    __syncthreads();

    // ---- phase 2: suffix scan -> bstart (in place) + cutoff ----
    uint4 hv = ((const uint4*)sh)[tid];
    unsigned tot = hv.x + hv.y + hv.z + hv.w;
    unsigned suf = tot;
    #pragma unroll
    for (int d = 1; d < 32; d <<= 1) {
        unsigned v = __shfl_down_sync(FULLM, suf, d);
        if (lane + d < 32) suf += v;
    }
    if (lane == 0) wsum[wid] = suf;
    __syncthreads();
    if (tid < 32) {
        unsigned v  = wsum[tid];
        unsigned sv = v;
        #pragma unroll
        for (int d = 1; d < 32; d <<= 1) {
            unsigned u = __shfl_down_sync(FULLM, sv, d);
            if (tid + d < 32) sv += u;
        }
        wsum[tid] = sv - v;
    }
    __syncthreads();
    unsigned run = wsum[wid] + (suf - tot);
    unsigned e3 = run;
    unsigned e2 = e3 + hv.w;
    unsigned e1 = e2 + hv.z;
    unsigned e0 = e1 + hv.y;
    uint4 ev = make_uint4(e0, e1, e2, e3);
    ((uint4*)sh)[tid]   = ev;   // bstart
    ((uint4*)scur)[tid] = ev;   // cursor init
    if      (e3 + hv.w >= (unsigned)KTOP) atomicMax(&sb, 4 * tid + 3);
    else if (e2 + hv.z >= (unsigned)KTOP) atomicMax(&sb, 4 * tid + 2);
    else if (e1 + hv.y >= (unsigned)KTOP) atomicMax(&sb, 4 * tid + 1);
    else if (e0 + hv.x >= (unsigned)KTOP) atomicMax(&sb, 4 * tid + 0);
    __syncthreads();
    const int cutoff = sb;
    const int nall   = min(s_nall, ALLCAP);

    // ---- phase 3: scatter from compact list (L2-hot, 8B coalesced) ----
    for (int p = tid; p < nall; p += 1024) {
        unsigned long long key = alist[p];
        float s = inv_ordkey((unsigned)(key >> 16));
        int b = bucket_of(s);
        if (b >= cutoff) {
            unsigned pos = atomicAdd(&scur[b], 1u);
            if (pos < CAP) skeys[pos] = key;
        }
    }
    __syncthreads();

    // ---- phase 4: exact within-bucket rank -> g_keys2 sorted desc ----
    const int ntot = min((int)scur[cutoff], CAP);
    for (int p = tid; p < ntot; p += 1024) {
        unsigned long long key = skeys[p];
        float sc = inv_ordkey((unsigned)(key >> 16));
        int b   = bucket_of(sc);
        int st2 = (int)sh[b];
        int en2 = min((int)scur[b], CAP);
        int rank = st2;
        for (int q = st2; q < en2; q++) rank += (skeys[q] > key) ? 1 : 0;
        g_keys2[(size_t)img * CAP + rank] = key;
    }
    for (int p = ntot + tid; p < CAP; p += 1024)
        g_keys2[(size_t)img * CAP + p] = 0ull;
    __syncthreads();

    // ---- phase 5: decode top-512 boxes ONCE ----
    if (tid < NSEL) {
        unsigned long long key = g_keys2[(size_t)img * CAP + tid];
        float4 b; float ar;
        decode_box(pimg, key, b, ar);
        g_b512[img * NSEL + tid] = b;
        g_a512[img * NSEL + tid] = ar;
    }
    if (tid == 0) g_ntot[img] = ntot;
}

// ================= K2: parallel 512x512 suppression matrix; last block resolves =================
// smem layout (bytes)
#define M_SBOX  0                        // 512*16 = 8192
#define M_SAREA 8192                     // 512*4  = 2048
#define M_SKEY  10240                    // 512*8  = 4096
#define M_SMAT  14336                    // 512*16*4 = 32768
#define M_LBOX  47104                    // 336*16 = 5376
#define M_LAREA 52480                    // 336*4  = 1344
#define M_LKEY  53824                    // 336*8  = 2688
#define M_TOTAL 56512

__global__ void __launch_bounds__(1024) k_matres(const float* __restrict__ preds) {
    extern __shared__ char sm[];
    float4*             sbox  = (float4*)(sm + M_SBOX);
    float*              sarea = (float*)(sm + M_SAREA);
    unsigned long long* skey  = (unsigned long long*)(sm + M_SKEY);
    unsigned*           smat  = (unsigned*)(sm + M_SMAT);
    float4*             lbox  = (float4*)(sm + M_LBOX);
    float*              slar  = (float*)(sm + M_LAREA);
    unsigned long long* lkey  = (unsigned long long*)(sm + M_LKEY);
    __shared__ unsigned sValid[NW], sSall[NW], sKept0[NW], sK0[NW], sKept[NW], sPref[NW];
    __shared__ int s_cur, slast;

    const int img  = blockIdx.x >> 3;
    const int part = blockIdx.x & 7;
    const int tid  = threadIdx.x;
    const int lane = tid & 31;
    const int w    = tid >> 5;
    const float* pimg = preds + (size_t)img * NCH * NANCH;
    const int ntot = g_ntot[img];

    // ---- load top-512 candidates (coalesced, decoded once in K1) ----
    if (tid < NSEL) {
        skey[tid]  = g_keys2[(size_t)img * CAP + tid];
        sbox[tid]  = g_b512[img * NSEL + tid];
        sarea[tid] = g_a512[img * NSEL + tid];
    }
    __syncthreads();

    // ---- slab of upper-triangular suppression matrix ----
    {
        const int cw   = w & 15;
        const int half = w >> 4;
        const int j    = cw * 32 + lane;
        float4 bj = sbox[j];
        float  aj = sarea[j];
        const int i0 = part * 64 + half * 32;
        #pragma unroll 4
        for (int r = 0; r < 32; r++) {
            const int i = i0 + r;
            if (cw >= (i >> 5)) {
                float4 bi = sbox[i];
                float  ai = sarea[i];
                bool bit = (j > i) && sup_test(bi.x, bi.y, bi.z, bi.w, ai,
                                               bj.x, bj.y, bj.z, bj.w, aj);
                unsigned bm = __ballot_sync(FULLM, bit);
                if (lane == 0) g_mat[((size_t)img * NSEL + i) * NW + cw] = bm;
            }
        }
    }
    __syncthreads();
    if (tid == 0) {
        __threadfence();
        slast = (atomicAdd(&g_done3[img], 1u) == BPIM - 1);
    }
    __syncthreads();
    if (!slast) return;

    // ---- last block: exact greedy resolve via bit algebra ----
    __threadfence();
    if (tid == 0) { g_done3[img] = 0u; s_cur = 0; }
    for (int idx = tid; idx < NSEL * NW; idx += 1024)
        smat[idx] = g_mat[(size_t)img * NSEL * NW + idx];
    __syncthreads();

    if (w < NW) {
        int c = w * 32 + lane;
        bool valid = (c < ntot) && (skey[c] != 0ull);
        unsigned vb = __ballot_sync(FULLM, valid);
        if (lane == 0) sValid[w] = vb;
    }
    __syncthreads();
    if (w < NW) {
        unsigned acc = 0;
        for (int k = 0; k <= w; k++) {
            int c = k * 32 + lane;
            if ((sValid[k] >> lane) & 1u) acc |= smat[c * NW + w];
        }
        acc = __reduce_or_sync(FULLM, acc);
        if (lane == 0) sSall[w] = acc;
    }
    __syncthreads();
    if (w < NW && lane == 0) sKept0[w] = sValid[w] & ~sSall[w];
    __syncthreads();
    if (w < NW) {
        unsigned acc = 0;
        for (int k = 0; k <= w; k++) {
            int c = k * 32 + lane;
            if ((sKept0[k] >> lane) & 1u) acc |= smat[c * NW + w];
        }
        acc = __reduce_or_sync(FULLM, acc);
        if (lane == 0) sK0[w] = acc;
    }
    __syncthreads();

    if (tid < 32) {
        unsigned Sck = 0;
        unsigned keptReg = 0;
        for (int m = 0; m < NW; m++) {
            unsigned cont = sValid[m] & sSall[m];
            unsigned kc = 0;
            while (cont) {
                int bit = __ffs(cont) - 1;
                cont &= cont - 1u;
                int c = m * 32 + bit;
                unsigned sckm = __shfl_sync(FULLM, Sck, m);
                bool suppressed = (((sK0[m] | sckm) >> bit) & 1u) != 0u;
                if (!suppressed) {
                    kc |= 1u << bit;
                    if (lane < NW && lane >= m) Sck |= smat[c * NW + lane];
                }
            }
            unsigned kw = (sValid[m] & ~sSall[m]) | kc;
            if (lane == m) keptReg = kw;
        }
        int cntw = __popc((lane < NW) ? keptReg : 0u);
        int inc = cntw;
        #pragma unroll
        for (int d = 1; d < 32; d <<= 1) {
            int v = __shfl_up_sync(FULLM, inc, d);
            if (lane >= d) inc += v;
        }
        if (lane < NW) { sKept[lane] = keptReg; sPref[lane] = inc - cntw; }
        if (lane == 31) s_cur = inc;
    }
    __syncthreads();

    if (tid < NSEL) {
        int wrd = tid >> 5;
        int l   = tid & 31;
        unsigned km = sKept[wrd];
        if ((km >> l) & 1u) {
            int rank = (int)sPref[wrd] + __popc(km & ((1u << l) - 1u));
            if (rank < LCAPE) {
                lbox[rank] = sbox[tid];
                slar[rank] = sarea[tid];
                lkey[rank] = skey[tid];
            }
        }
    }
    __syncthreads();

    // exact fallback: continue past NSEL if fewer than MAXDET kept (rare/never)
    if (tid < 32) {
        int curf = s_cur;
        int lim  = min(min(ntot, CAP), KTOP);
        if (curf < MAXDET && lim > NSEL) {
            for (int c = NSEL; c < lim && curf < MAXDET; c++) {
                unsigned long long key = g_keys2[(size_t)img * CAP + c];
                if (key == 0ull) continue;
                float4 bc; float ac;
                decode_box(pimg, key, bc, ac);
                bool sup = false;
                for (int l = lane; l < curf; l += 32) {
                    float4 bl = lbox[l];
                    sup |= sup_test(bl.x, bl.y, bl.z, bl.w, slar[l],
                                    bc.x, bc.y, bc.z, bc.w, ac);
                }
                if (!__any_sync(FULLM, sup)) {
                    if (lane == 0 && curf < LCAPE) {
                        lbox[curf] = bc; slar[curf] = ac; lkey[curf] = key;
                    }
                    __syncwarp();
                    curf++;
                }
            }
        }
        if (lane == 0) s_cur = curf;
    }
    __syncthreads();

    const int cnt = min(s_cur, MAXDET);
    if (tid < cnt) {
        unsigned long long key = lkey[tid];
        g_selbox  [img * MAXDET + tid] = lbox[tid];
        g_selscore[img * MAXDET + tid] = inv_ordkey((unsigned)(key >> 16));
        g_selanch [img * MAXDET + tid] = 65535 - (int)(key & 0xFFFFull);
    }
    if (tid == 0) g_cnt[img] = cnt;
}

// ================= K3: wide output writer =================
#define TOTOUT (BS * MAXDET * 56)
__global__ void __launch_bounds__(1024) k_out(const float* __restrict__ preds,
                                              float* __restrict__ out) {
    int s = blockIdx.x * 1024 + threadIdx.x;
    if (s >= TOTOUT) return;
    const int img = s / (MAXDET * 56);
    const int rem = s % (MAXDET * 56);
    const int r   = rem / 56;
    const int f   = rem % 56;
    const int cnt = g_cnt[img];

    float v = 0.0f;
    if (r < cnt) {
        if (f < 4) {
            float4 b = g_selbox[img * MAXDET + r];
            v = (f == 0) ? b.x : (f == 1) ? b.y : (f == 2) ? b.z : b.w;
        } else if (f == 4) {
            v = g_selscore[img * MAXDET + r];
        } else {
            int c = f - 5;
            int a = g_selanch[img * MAXDET + r];
            v = preds[(size_t)img * NCH * NANCH + (size_t)(5 + c) * NANCH + a];
            if (c < 2) v = fminf(fmaxf(v, 0.0f), IMGW);
        }
    }
    const int OSC = BS * MAXDET * 4;
    const int OKP = OSC + BS * MAXDET;
    if (f < 4)       out[(img * MAXDET + r) * 4 + f] = v;
    else if (f == 4) out[OSC + img * MAXDET + r] = v;
    else             out[OKP + (img * MAXDET + r) * 51 + (f - 5)] = v;
}

// ---------------- launch ----------------
extern "C" void kernel_launch(void* const* d_in, const int* in_sizes, int n_in,
                              void* d_out, int out_size) {
    const float* preds = (const float*)d_in[0];
    float* out = (float*)d_out;
    cudaFuncSetAttribute(k_front,  cudaFuncAttributeMaxDynamicSharedMemorySize, F_SMEM);
    cudaFuncSetAttribute(k_matres, cudaFuncAttributeMaxDynamicSharedMemorySize, M_TOTAL);
    k_front <<<BS, 1024, F_SMEM>>>(preds);
    k_matres<<<BS * BPIM, 1024, M_TOTAL>>>(preds);
    k_out   <<<(TOTOUT + 1023) / 1024, 1024>>>(preds, out);
}